// round 16
// baseline (speedup 1.0000x reference)
#include <cuda_runtime.h>
#include <cuda_bf16.h>
#include <cstdint>

#define BLK    512
#define NWARP  (BLK / 32)
#define DP     4               // prefetch depth (tiles per warp in flight)
#define NB     10

#define N_POS_MAX  100000
#define N_QPOS_MAX 10000

// FC = 1.14136 * e^2 * sqrt(10)
#define FC_CONST 26.6692997f
#define SQRT3_F  1.7320508075688772f

// Padded pos table (16B rows -> single LDG.128 per gather).
__device__ float4 g_pos4[N_POS_MAX];

__global__ void pad_pos_kernel(const float* __restrict__ pos, int n_pos)
{
    int i = blockIdx.x * blockDim.x + threadIdx.x;
    if (i < n_pos)
        g_pos4[i] = make_float4(pos[3*i], pos[3*i+1], pos[3*i+2], 0.f);
}

__device__ __forceinline__ uint32_t smem_u32(const void* p) {
    uint32_t a;
    asm("{ .reg .u64 t; cvta.to.shared.u64 t, %1; cvt.u32.u64 %0, t; }"
        : "=r"(a) : "l"(p));
    return a;
}

// Per-warp staging slot: 32 edges * (9 sh + 10 emb) floats = 608 floats = 2432 B
#define SLOT_FLOATS   608
#define SLOT_SH       0
#define SLOT_EMB      288
#define STAGE_FLOATS  (NWARP * 2 * SLOT_FLOATS)
#define SMEM_STAGE_BYTES (STAGE_FLOATS * 4)                 // 77,824 B
#define SMEM_Q_BYTES     (3 * N_QPOS_MAX * 4)               // 120,000 B
#define SMEM_TOTAL       (SMEM_STAGE_BYTES + SMEM_Q_BYTES)  // 197,824 B

__global__ void __launch_bounds__(BLK, 1) qsh_kernel(
    const int*   __restrict__ esrc,    // [E] -> qpos rows
    const int*   __restrict__ edst,    // [E] -> pos rows
    const float* __restrict__ qpos,    // [n_qpos*3] raw (copied to SMEM)
    float*       __restrict__ out,     // [E*9] sh | [E*10] embed
    int E, int n_qpos)
{
    extern __shared__ __align__(16) char smem[];
    float* s_stage = (float*)smem;
    float* s_qx    = (float*)(smem + SMEM_STAGE_BYTES);
    float* s_qy    = s_qx + N_QPOS_MAX;
    float* s_qz    = s_qy + N_QPOS_MAX;

    const int t    = threadIdx.x;
    const int wid  = t >> 5;
    const int lane = t & 31;

    // ---- one-time: qpos table -> SMEM (SoA) ----
    for (int i = t; i < n_qpos * 3; i += BLK) {
        float v = qpos[i];
        int r = i / 3, c = i - 3 * r;
        float* dst = (c == 0) ? s_qx : (c == 1) ? s_qy : s_qz;
        dst[r] = v;
    }
    __syncthreads();   // only CTA-wide barrier in the kernel

    float* out_sh  = out;
    float* out_emb = out + (long long)E * 9;
    const bool aligned4 = ((E & 3) == 0);

    const long long nT = ((long long)E + 31) >> 5;              // 32-edge tiles
    const long long W  = (long long)gridDim.x * NWARP;          // total warps
    const long long gw = (long long)blockIdx.x * NWARP + wid;   // my warp id

    // ---- depth-DP prefetch of indices + pos gathers ----
    int    si_p[DP], di_p[DP];
    float4 b_p[DP];
    #pragma unroll
    for (int d = 0; d < DP; d++) {
        long long tile = gw + (long long)d * W;
        long long e = tile * 32 + lane;
        bool v = (tile < nT) && (e < (long long)E);
        si_p[d] = v ? esrc[e] : 0;
        di_p[d] = v ? edst[e] : 0;
    }
    #pragma unroll
    for (int d = 0; d < DP; d++)
        b_p[d] = __ldg(&g_pos4[di_p[d]]);

    int cur = 0;
    long long k = 0;
    for (long long tile = gw; tile < nT; tile += W, k++) {
        // consume current prefetch entry
        const int    si = si_p[cur];
        const float4 b  = b_p[cur];

        // refill this entry with tile + DP*W
        {
            long long pt = tile + (long long)DP * W;
            long long e  = pt * 32 + lane;
            bool v = (pt < nT) && (e < (long long)E);
            int s = v ? esrc[e] : 0;
            int d = v ? edst[e] : 0;
            si_p[cur] = s;
            di_p[cur] = d;
            b_p[cur]  = __ldg(&g_pos4[d]);
        }
        cur = (cur + 1) & (DP - 1);

        // ---- compute ----
        const float vx = s_qx[si] - b.x;
        const float vy = s_qy[si] - b.y;
        const float vz = s_qz[si] - b.z;

        const float s2   = vx*vx + vy*vy + vz*vz;
        const float rinv = (s2 > 0.f) ? rsqrtf(s2) : 0.f;
        const float r    = s2 * rinv;
        const float x = vx * rinv, y = vy * rinv, z = vz * rinv;

        const float sh4 = SQRT3_F * x * z;
        const float sh5 = SQRT3_F * x * y;
        const float sh6 = y*y - 0.5f * (x*x + z*z);
        const float sh7 = SQRT3_F * y * z;
        const float sh8 = 0.5f * SQRT3_F * (z*z - x*x);

        // embed: d_j = 11r-(j+1); |d_j|<1; at most 2 of 10 nonzero.
        // sus(1+d)*sus(1-d) = exp(-2/(1-d^2))
        const float tt = r * 11.0f;
        const int   kk = (int)tt;
        const float d1 = tt - (float)kk;
        const float d2 = d1 - 1.f;
        float v1 = 0.f, v2 = 0.f;
        if (kk >= 1 && kk <= NB) v1 = FC_CONST * __expf(-2.f / (1.f - d1*d1));
        if (kk < NB && d2 > -1.f) v2 = FC_CONST * __expf(-2.f / (1.f - d2*d2));
        const int k1 = kk - 1, k2 = kk;

        const long long ebase = tile * 32;
        const int nval = (int)min(32LL, (long long)E - ebase);

        if (nval == 32 && aligned4) {
            // ---- warp-private staging + per-warp TMA drain (no bar.sync) ----
            const int slot = (int)(k & 1);
            float* st = s_stage + ((wid << 1) + slot) * SLOT_FLOATS;

            // slot free when the group committed 2 tiles ago has read-completed
            if (lane == 0)
                asm volatile("cp.async.bulk.wait_group.read 1;" ::: "memory");
            __syncwarp();

            float* msh = st + SLOT_SH + lane * 9;       // stride 9: conflict-free
            msh[0] = 1.f;  msh[1] = x;  msh[2] = y;  msh[3] = z;
            msh[4] = sh4;  msh[5] = sh5; msh[6] = sh6;
            msh[7] = sh7;  msh[8] = sh8;

            float* memb = st + SLOT_EMB + lane * NB;    // stride 10: ~2-way
            #pragma unroll
            for (int j = 0; j < NB; j++)
                memb[j] = (j == k1) ? v1 : ((j == k2) ? v2 : 0.f);

            __syncwarp();

            if (lane == 0) {
                asm volatile("fence.proxy.async.shared::cta;" ::: "memory");
                void* gsh = (void*)(out_sh  + ebase * 9);
                void* gem = (void*)(out_emb + ebase * NB);
                uint32_t ssh = smem_u32(st + SLOT_SH);
                uint32_t sem = smem_u32(st + SLOT_EMB);
                asm volatile(
                    "cp.async.bulk.global.shared::cta.bulk_group [%0], [%1], %2;"
                    :: "l"(gsh), "r"(ssh), "r"((uint32_t)(32 * 9 * 4)) : "memory");
                asm volatile(
                    "cp.async.bulk.global.shared::cta.bulk_group [%0], [%1], %2;"
                    :: "l"(gem), "r"(sem), "r"((uint32_t)(32 * NB * 4)) : "memory");
                asm volatile("cp.async.bulk.commit_group;" ::: "memory");
            }
        } else {
            // tail / unaligned fallback: direct scalar stores
            if (lane < nval) {
                long long e = ebase + lane;
                float* osh = out_sh + e * 9;
                osh[0] = 1.f; osh[1] = x; osh[2] = y; osh[3] = z;
                osh[4] = sh4; osh[5] = sh5; osh[6] = sh6;
                osh[7] = sh7; osh[8] = sh8;
                float* oem = out_emb + e * NB;
                #pragma unroll
                for (int j = 0; j < NB; j++)
                    oem[j] = (j == k1) ? v1 : ((j == k2) ? v2 : 0.f);
            }
        }
    }

    // drain all outstanding TMA groups before exit
    if (lane == 0)
        asm volatile("cp.async.bulk.wait_group 0;" ::: "memory");
}

extern "C" void kernel_launch(void* const* d_in, const int* in_sizes, int n_in,
                              void* d_out, int out_size)
{
    const float* pos  = (const float*)d_in[0];
    const float* qpos = (const float*)d_in[1];
    const int*   esrc = (const int*)  d_in[2];
    const int*   edst = (const int*)  d_in[3];

    const int n_pos  = in_sizes[0] / 3;
    const int n_qpos = in_sizes[1] / 3;
    const int E      = in_sizes[2];

    pad_pos_kernel<<<(n_pos + 255) / 256, 256>>>(pos, n_pos);

    static int sm_count = 0;
    if (sm_count == 0) {
        int dev = 0;
        cudaGetDevice(&dev);
        cudaDeviceGetAttribute(&sm_count, cudaDevAttrMultiProcessorCount, dev);
        cudaFuncSetAttribute(qsh_kernel,
                             cudaFuncAttributeMaxDynamicSharedMemorySize,
                             SMEM_TOTAL);
    }

    const long long nT = ((long long)E + 31) >> 5;
    long long needed = (nT + NWARP - 1) / NWARP;
    int grid = (int)((needed < (long long)sm_count) ? needed : (long long)sm_count);

    qsh_kernel<<<grid, BLK, SMEM_TOTAL>>>(esrc, edst, qpos, (float*)d_out,
                                          E, n_qpos);
}